// round 17
// baseline (speedup 1.0000x reference)
#include <cuda_runtime.h>
#include <cuda_bf16.h>
#include <cstdint>

#define MTILE 64
#define NTILES 7820

struct AdjPtrs { const int* p[10]; };

__device__ __align__(1024) unsigned char g_Wh[11][8][8192];
__device__ __align__(1024) unsigned char g_Wl[11][8][8192];
__device__ float g_bias[11][128];

__device__ __forceinline__ uint32_t smem_u32(const void* p) {
    uint32_t a;
    asm("{ .reg .u64 t; cvta.to.shared.u64 t, %1; cvt.u32.u64 %0, t; }" : "=r"(a) : "l"(p));
    return a;
}
__device__ __forceinline__ void ldsm4(uint32_t* r, uint32_t a) {
    asm volatile("ldmatrix.sync.aligned.m8n8.x4.shared.b16 {%0,%1,%2,%3}, [%4];"
        : "=r"(r[0]), "=r"(r[1]), "=r"(r[2]), "=r"(r[3]) : "r"(a));
}
__device__ __forceinline__ void ldsm4t(uint32_t* r, uint32_t a) {
    asm volatile("ldmatrix.sync.aligned.m8n8.x4.trans.shared.b16 {%0,%1,%2,%3}, [%4];"
        : "=r"(r[0]), "=r"(r[1]), "=r"(r[2]), "=r"(r[3]) : "r"(a));
}
__device__ __forceinline__ void mma16816(float* c, const uint32_t* a, uint32_t b0, uint32_t b1) {
    asm volatile("mma.sync.aligned.m16n8k16.row.col.f32.bf16.bf16.f32 "
        "{%0,%1,%2,%3}, {%4,%5,%6,%7}, {%8,%9}, {%0,%1,%2,%3};"
        : "+f"(c[0]), "+f"(c[1]), "+f"(c[2]), "+f"(c[3])
        : "r"(a[0]), "r"(a[1]), "r"(a[2]), "r"(a[3]), "r"(b0), "r"(b1));
}
__device__ __forceinline__ void cpasync16(uint32_t dst, const void* src) {
    asm volatile("cp.async.cg.shared.global [%0], [%1], 16;" :: "r"(dst), "l"(src) : "memory");
}
#define CP_COMMIT() asm volatile("cp.async.commit_group;" ::: "memory")
#define CP_WAIT0()  asm volatile("cp.async.wait_group 0;" ::: "memory")

__device__ __forceinline__ unsigned long long pack4bf(float a0, float a1, float a2, float a3) {
    __nv_bfloat162 p0 = __floats2bfloat162_rn(a0, a1);
    __nv_bfloat162 p1 = __floats2bfloat162_rn(a2, a3);
    unsigned int u0 = *(unsigned int*)&p0;
    unsigned int u1 = *(unsigned int*)&p1;
    return (unsigned long long)u0 | ((unsigned long long)u1 << 32);
}

// split fp32x4 -> bf16 hi @p+off, residual lo @p+16384+off
__device__ __forceinline__ void split_store(unsigned char* p, int off, float4 v) {
    float h0 = __bfloat162float(__float2bfloat16(v.x));
    float h1 = __bfloat162float(__float2bfloat16(v.y));
    float h2 = __bfloat162float(__float2bfloat16(v.z));
    float h3 = __bfloat162float(__float2bfloat16(v.w));
    *(unsigned long long*)(p + off)         = pack4bf(v.x, v.y, v.z, v.w);
    *(unsigned long long*)(p + 16384 + off) = pack4bf(v.x - h0, v.y - h1, v.z - h2, v.w - h3);
}
__device__ __forceinline__ int aoff(int m, int lane) {
    return ((m * 256 + 8 * lane) ^ ((m & 7) << 4));
}

// ---------------- weight prep ----------------
__global__ void prep_weights(const float* __restrict__ W0,   const float* __restrict__ b0,
                             const float* __restrict__ Wrel, const float* __restrict__ brel,
                             const float* __restrict__ Wself,const float* __restrict__ bself)
{
    int idx = blockIdx.x * blockDim.x + threadIdx.x;
    if (idx >= 11 * 256 * 128) return;
    int n = idx & 127;
    int k = (idx >> 7) & 255;
    int s = idx >> 15;
    float w;
    if (s == 0) w = (k < 128) ? 0.f : W0[(size_t)(k - 128) * 128 + n];
    else        w = (k < 128) ? Wrel[((size_t)(s - 1) * 128 + k) * 128 + n]
                              : Wself[((size_t)(s - 1) * 128 + (k - 128)) * 128 + n];
    __nv_bfloat16 hi = __float2bfloat16(w);
    __nv_bfloat16 lo = __float2bfloat16(w - __bfloat162float(hi));
    int b = (((k & 31) * 256) + n * 2) ^ ((k & 7) << 4);
    *(__nv_bfloat16*)(g_Wh[s][k >> 5] + b) = hi;
    *(__nv_bfloat16*)(g_Wl[s][k >> 5] + b) = lo;
    if (k == 0) g_bias[s][n] = (s == 0) ? b0[n] : brel[(s - 1) * 128 + n] + bself[(s - 1) * 128 + n];
}

__device__ __forceinline__ void decode_tile(int t, int& seg, int& btile, int& row0, int& rows) {
    const int cnt[11] = {25000,50000,100000,150000,100000,50000,5000,5000,5000,5000,5000};
    const int off[11] = {0,25000,75000,175000,325000,425000,475000,480000,485000,490000,495000};
    int s = 0, b = t;
    while (true) { int n = (cnt[s] + 63) >> 6; if (b < n) break; b -= n; ++s; }
    seg = s; btile = b; row0 = off[s] + b * 64; rows = min(64, cnt[s] - b * 64);
}

// ---------------- inline gather (fallback path, from R13) --------------------------
template<int DEG>
__device__ __forceinline__ void gather_rel_inl(const float* __restrict__ af,
                                               const int* __restrict__ adjp,
                                               unsigned char* __restrict__ Rp,
                                               int rows, int wrp, int lane)
{
    const int k0 = lane * 4;
    constexpr int NI = 8 * DEG;
    constexpr int NR = (NI + 31) / 32;
    int ridx[NR];
    const int liveRows = min(max(rows - wrp * 8, 0), 8);
    const int nlive = liveRows * DEG;
    const int* base = adjp + (wrp * 8) * DEG;
    #pragma unroll
    for (int r = 0; r < NR; ++r) {
        int e = lane + r * 32;
        ridx[r] = (e < nlive) ? __ldg(base + e) : 0;
    }
    constexpr int UN = (DEG <= 1) ? 8 : (DEG <= 3) ? 4 : (DEG <= 5) ? 2 : 1;
    #pragma unroll
    for (int ii = 0; ii < 8; ii += UN) {
        float4 nb[UN][DEG];
        #pragma unroll
        for (int u = 0; u < UN; ++u)
            #pragma unroll
            for (int j = 0; j < DEG; ++j) {
                const int flat = (ii + u) * DEG + j;
                int idx = __shfl_sync(0xffffffffu, ridx[flat >> 5], flat & 31);
                nb[u][j] = *(const float4*)(af + (size_t)idx * 128 + k0);
            }
        #pragma unroll
        for (int u = 0; u < UN; ++u) {
            int m = wrp * 8 + ii + u;
            if (m >= rows) continue;
            float4 r4 = make_float4(0.f, 0.f, 0.f, 0.f);
            #pragma unroll
            for (int j = 0; j < DEG; ++j) {
                r4.x += nb[u][j].x; r4.y += nb[u][j].y;
                r4.z += nb[u][j].z; r4.w += nb[u][j].w;
            }
            constexpr float inv = 1.0f / (float)DEG;
            r4.x *= inv; r4.y *= inv; r4.z *= inv; r4.w *= inv;
            split_store(Rp, aoff(m, lane), r4);
        }
    }
}

__device__ __forceinline__ void load_self_inl(const float* __restrict__ af,
                                              unsigned char* __restrict__ Sp,
                                              int row0, int rows, int wrp, int lane)
{
    const int k0 = lane * 4;
    #pragma unroll 1
    for (int ii = 0; ii < 8; ii += 4) {
        float4 sv[4];
        #pragma unroll
        for (int u = 0; u < 4; ++u) {
            int m = wrp * 8 + ii + u;
            int ml = (m < rows) ? m : 0;
            sv[u] = *(const float4*)(af + (size_t)(row0 + ml) * 128 + k0);
        }
        #pragma unroll
        for (int u = 0; u < 4; ++u) {
            int m = wrp * 8 + ii + u;
            if (m < rows) split_store(Sp, aoff(m, lane), sv[u]);
        }
    }
}

__device__ __forceinline__ void prefetchB(int seg, int c, uint32_t dst, int tid) {
    const unsigned char* sh = g_Wh[seg][c];
    const unsigned char* sl = g_Wl[seg][c];
    cpasync16(dst + tid * 16,               sh + tid * 16);
    cpasync16(dst + 4096 + tid * 16,        sh + 4096 + tid * 16);
    cpasync16(dst + 8192 + tid * 16,        sl + tid * 16);
    cpasync16(dst + 8192 + 4096 + tid * 16, sl + 4096 + tid * 16);
}

// ---------------- persistent pipelined kernel ----------------
__global__ __launch_bounds__(256, 2)
void graphconv_pers(const float* __restrict__ af, AdjPtrs adj, float* __restrict__ out)
{
    extern __shared__ unsigned char dynsmem[];
    uint32_t base0 = smem_u32(dynsmem);
    uint32_t Rbase = (base0 + 1023) & ~1023u;   // REL: hi 16KB + lo 16KB
    uint32_t Sbase = Rbase + 32768;             // SELF: hi 16KB + lo 16KB
    uint32_t Bbase = Rbase + 65536;             // B: 2 x 16KB
    unsigned char* Rp = dynsmem + (Rbase - base0);
    unsigned char* Sp = dynsmem + (Sbase - base0);

    const int tid  = threadIdx.x;
    const int lane = tid & 31;
    const int wrp  = tid >> 5;
    const int wm = wrp >> 2;
    const int wn = wrp & 3;
    const int arow0 = wm * 32 + (lane & 15);
    const int aswz  = (arow0 & 7) << 4;
    const int aLow  = (lane >> 4) << 4;
    const int bswz = (lane & 7) << 4;
    const int bn   = wn * 32 + 8 * (lane >> 4);
    const uint32_t bOff0 = (lane & 15) * 256 + (uint32_t)(((bn +  0) * 2) ^ bswz);
    const uint32_t bOff1 = (lane & 15) * 256 + (uint32_t)(((bn + 16) * 2) ^ bswz);
    const int k0 = lane * 4;

    // preamble: B chunk for first tile
    {
        int seg0, bt0, r00, rw0;
        if (blockIdx.x < NTILES) {
            decode_tile(blockIdx.x, seg0, bt0, r00, rw0);
            int c00 = (seg0 == 0) ? 4 : 0;
            prefetchB(seg0, c00, Bbase + ((c00 & 1) * 16384), tid);
            CP_COMMIT();
        }
    }

    bool cur_pip = false;

    #pragma unroll 1
    for (int t = blockIdx.x; t < NTILES; t += gridDim.x) {
        int seg, btile, row0, rows;
        decode_tile(t, seg, btile, row0, rows);
        const int deg = seg;
        const int c0  = (deg == 0) ? 4 : 0;
        const int nch = 8 - c0;

        const int tn = t + gridDim.x;
        const bool has_nxt = tn < NTILES;
        int segN = 0, btileN = 0, row0N = 0, rowsN = 0;
        if (has_nxt) decode_tile(tn, segN, btileN, row0N, rowsN);
        const int degN = segN;
        const int c0N  = (degN == 0) ? 4 : 0;
        const bool nxt_pip = has_nxt && (deg > 0) && (degN >= 1) && (degN <= 3);

        // ---- inline gather for current tile if it wasn't pipelined ----
        if (!cur_pip) {
            if (deg > 0) {
                const int* adjp = adj.p[deg - 1] + (size_t)(btile * 64) * deg;
                switch (deg) {
                    case 1:  gather_rel_inl<1 >(af, adjp, Rp, rows, wrp, lane); break;
                    case 2:  gather_rel_inl<2 >(af, adjp, Rp, rows, wrp, lane); break;
                    case 3:  gather_rel_inl<3 >(af, adjp, Rp, rows, wrp, lane); break;
                    case 4:  gather_rel_inl<4 >(af, adjp, Rp, rows, wrp, lane); break;
                    case 5:  gather_rel_inl<5 >(af, adjp, Rp, rows, wrp, lane); break;
                    case 6:  gather_rel_inl<6 >(af, adjp, Rp, rows, wrp, lane); break;
                    case 7:  gather_rel_inl<7 >(af, adjp, Rp, rows, wrp, lane); break;
                    case 8:  gather_rel_inl<8 >(af, adjp, Rp, rows, wrp, lane); break;
                    case 9:  gather_rel_inl<9 >(af, adjp, Rp, rows, wrp, lane); break;
                    default: gather_rel_inl<10>(af, adjp, Rp, rows, wrp, lane); break;
                }
            }
            load_self_inl(af, Sp, row0, rows, wrp, lane);
        }

        // ---- idx prefetch for pipelined next tile ----
        int ridxN = 0, nliveN = 0;
        float invN = 1.f;
        if (nxt_pip) {
            const int* adjbN = adj.p[degN - 1] + (size_t)(btileN * 64) * degN + (wrp * 8) * degN;
            int liveRowsN = min(max(rowsN - wrp * 8, 0), 8);
            nliveN = liveRowsN * degN;
            ridxN = (lane < nliveN) ? __ldg(adjbN + lane) : 0;
            invN = 1.0f / (float)degN;
        }

        float4 stg[4][3];
        float4 sst[8];

        float acc[2][4][4];
        #pragma unroll
        for (int a = 0; a < 2; ++a)
            #pragma unroll
            for (int b = 0; b < 4; ++b)
                #pragma unroll
                for (int v = 0; v < 4; ++v) acc[a][b][v] = 0.f;

        // ---- GEMM chunk loop with pipeline hooks ----
        #pragma unroll 1
        for (int ci = 0; ci < nch; ++ci) {
            const int c = c0 + ci;

            CP_WAIT0();
            __syncthreads();

            if (nxt_pip) {
                if (ci == 2) {
                    // issue rel half1 loads (rows 0..3 of this warp's 8)
                    #pragma unroll
                    for (int u = 0; u < 4; ++u)
                        #pragma unroll
                        for (int j = 0; j < 3; ++j)
                            if (j < degN) {
                                int idx = __shfl_sync(0xffffffffu, ridxN, u * degN + j);
                                stg[u][j] = *(const float4*)(af + (size_t)idx * 128 + k0);
                            }
                } else if (ci == 4) {
                    // store half1 into REL buf (chunks 0-3 reads done at sync above)
                    #pragma unroll
                    for (int u = 0; u < 4; ++u) {
                        int m = wrp * 8 + u;
                        if (m < rowsN) {
                            float4 r4 = stg[u][0];
                            if (degN > 1) { r4.x += stg[u][1].x; r4.y += stg[u][1].y; r4.z += stg[u][1].z; r4.w += stg[u][1].w; }
                            if (degN > 2) { r4.x += stg[u][2].x; r4.y += stg[u][2].y; r4.z += stg[u][2].z; r4.w += stg[u][2].w; }
                            r4.x *= invN; r4.y *= invN; r4.z *= invN; r4.w *= invN;
                            split_store(Rp, aoff(m, lane), r4);
                        }
                    }
                    // issue rel half2 loads (rows 4..7)
                    #pragma unroll
                    for (int u = 0; u < 4; ++u)
                        #pragma unroll
                        for (int j = 0; j < 3; ++j)
                            if (j < degN) {
                                int idx = __shfl_sync(0xffffffffu, ridxN, (u + 4) * degN + j);
                                stg[u][j] = *(const float4*)(af + (size_t)idx * 128 + k0);
                            }
                } else if (ci == 6) {
                    // store half2
                    #pragma unroll
                    for (int u = 0; u < 4; ++u) {
                        int m = wrp * 8 + 4 + u;
                        if (m < rowsN) {
                            float4 r4 = stg[u][0];
                            if (degN > 1) { r4.x += stg[u][1].x; r4.y += stg[u][1].y; r4.z += stg[u][1].z; r4.w += stg[u][1].w; }
                            if (degN > 2) { r4.x += stg[u][2].x; r4.y += stg[u][2].y; r4.z += stg[u][2].z; r4.w += stg[u][2].w; }
                            r4.x *= invN; r4.y *= invN; r4.z *= invN; r4.w *= invN;
                            split_store(Rp, aoff(m, lane), r4);
                        }
                    }
                    // issue self loads for next tile
                    #pragma unroll
                    for (int u = 0; u < 8; ++u) {
                        int m = wrp * 8 + u;
                        int ml = (m < rowsN) ? m : 0;
                        sst[u] = *(const float4*)(af + (size_t)(row0N + ml) * 128 + k0);
                    }
                }
            }

            if (ci + 1 < nch) {
                prefetchB(seg, c + 1, Bbase + (((c + 1) & 1) * 16384), tid);
                CP_COMMIT();
            } else if (has_nxt) {
                prefetchB(segN, c0N, Bbase + ((c0N & 1) * 16384), tid);
                CP_COMMIT();
            }

            const uint32_t abuf = (c < 4) ? Rbase : Sbase;
            const uint32_t aB0 = abuf + arow0 * 256;
            const uint32_t aB1 = aB0 + 16 * 256;
            const uint32_t bufo = (uint32_t)(c & 1) * 16384;
            const int klb = (c & 3) * 32;
            #pragma unroll
            for (int klh = 0; klh < 2; ++klh) {
                const int kl = klh * 16;
                uint32_t ah0[4], ah1[4], al0[4], al1[4];
                const uint32_t ak = (uint32_t)((aLow + (klb + kl) * 2) ^ aswz);
                ldsm4(ah0, aB0 + ak);
                ldsm4(ah1, aB1 + ak);
                ldsm4(al0, aB0 + 16384 + ak);
                ldsm4(al1, aB1 + 16384 + ak);
                #pragma unroll
                for (int p = 0; p < 2; ++p) {
                    uint32_t bh[4], bl[4];
                    uint32_t ba = Bbase + bufo + (uint32_t)(kl * 256) + (p ? bOff1 : bOff0);
                    ldsm4t(bh, ba);
                    ldsm4t(bl, ba + 8192);
                    const int n0 = 2 * p, n1 = 2 * p + 1;
                    mma16816(acc[0][n0], ah0, bh[0], bh[1]);
                    mma16816(acc[0][n1], ah0, bh[2], bh[3]);
                    mma16816(acc[1][n0], ah1, bh[0], bh[1]);
                    mma16816(acc[1][n1], ah1, bh[2], bh[3]);
                    mma16816(acc[0][n0], al0, bh[0], bh[1]);
                    mma16816(acc[0][n1], al0, bh[2], bh[3]);
                    mma16816(acc[1][n0], al1, bh[0], bh[1]);
                    mma16816(acc[1][n1], al1, bh[2], bh[3]);
                    mma16816(acc[0][n0], ah0, bl[0], bl[1]);
                    mma16816(acc[0][n1], ah0, bl[2], bl[3]);
                    mma16816(acc[1][n0], ah1, bl[0], bl[1]);
                    mma16816(acc[1][n1], ah1, bl[2], bl[3]);
                }
            }
        }

        __syncthreads();   // all chunk reads done (REL & SELF)

        if (nxt_pip) {
            #pragma unroll
            for (int u = 0; u < 8; ++u) {
                int m = wrp * 8 + u;
                if (m < rowsN) split_store(Sp, aoff(m, lane), sst[u]);
            }
        }

        // ---- epilogue: bias + ReLU + store ----
        const int colb = wn * 32 + 2 * (lane & 3);
        #pragma unroll
        for (int mt = 0; mt < 2; ++mt) {
            const int rbase = wm * 32 + mt * 16 + (lane >> 2);
            #pragma unroll
            for (int h = 0; h < 2; ++h) {
                const int m = rbase + h * 8;
                if (m < rows) {
                    float* orow = out + (size_t)(row0 + m) * 128;
                    #pragma unroll
                    for (int nt = 0; nt < 4; ++nt) {
                        const int col = colb + nt * 8;
                        float2 b2 = *(const float2*)&g_bias[seg][col];
                        float2 o;
                        o.x = fmaxf(acc[mt][nt][h * 2 + 0] + b2.x, 0.f);
                        o.y = fmaxf(acc[mt][nt][h * 2 + 1] + b2.y, 0.f);
                        *(float2*)(orow + col) = o;
                    }
                }
            }
        }

        cur_pip = nxt_pip;
    }
}

extern "C" void kernel_launch(void* const* d_in, const int* in_sizes, int n_in,
                              void* d_out, int out_size)
{
    const float* af = (const float*)d_in[0];
    AdjPtrs adj;
    for (int i = 0; i < 10; ++i) adj.p[i] = (const int*)d_in[2 + i];
    const float* W0    = (const float*)d_in[12];
    const float* b0    = (const float*)d_in[13];
    const float* Wrel  = (const float*)d_in[14];
    const float* brel  = (const float*)d_in[15];
    const float* Wself = (const float*)d_in[16];
    const float* bself = (const float*)d_in[17];
    float* out = (float*)d_out;

    prep_weights<<<(11 * 256 * 128 + 255) / 256, 256>>>(W0, b0, Wrel, brel, Wself, bself);

    int sms = 148;
    cudaDeviceGetAttribute(&sms, cudaDevAttrMultiProcessorCount, 0);
    int grid = sms * 2;

    size_t shmem = 32768 + 32768 + 32768 + 1024;  // REL + SELF + B + slack
    cudaFuncSetAttribute(graphconv_pers,
                         cudaFuncAttributeMaxDynamicSharedMemorySize, (int)shmem);
    graphconv_pers<<<grid, 256, shmem>>>(af, adj, out);
}